// round 1
// baseline (speedup 1.0000x reference)
#include <cuda_runtime.h>
#include <cstdint>

// BKT (2-state HMM) forward-backward.
// corr: (B,T) int32 ; dynamics_logits: (B,3) f32 ; obs_logits: (B,T,2) f32
// out: (3,B,T,2) f32 = [output_logprobs, state_posteriors, smoothed]

#define BN      8192
#define TT      1024
#define TC      16          // timesteps per staged chunk
#define NCH     (TT/TC)     // 64 chunks
#define THREADS 64
#define SA      33          // smem stride (32 payload + 1 pad) -> conflict-free scalar
#define SC      17          // corr smem stride

// scratch: [3][T][B] floats (t-major => coalesced across rows)
__device__ float g_scratch[(size_t)3 * TT * BN];

__global__ __launch_bounds__(THREADS, 1)
void bkt_kernel(const int* __restrict__ corr,
                const float* __restrict__ dyn,
                const float* __restrict__ obs,
                float* __restrict__ out)
{
    __shared__ float sA[THREADS * SA];   // obs staging -> pred staging (fwd), smoothed (bwd)
    __shared__ float sB[THREADS * SA];   // posts staging
    __shared__ int   sCc[THREADS * SC];  // corr staging

    const int tid  = threadIdx.x;
    const int row0 = blockIdx.x * THREADS;
    const int row  = row0 + tid;

    // ---- per-row parameters ----
    const float d0 = dyn[row * 3 + 0];
    const float d1 = dyn[row * 3 + 1];
    const float d2 = dyn[row * 3 + 2];
    const float ed0 = __expf(d0), ed1 = __expf(d1), ed2 = __expf(d2);
    const float ri0 = __frcp_rn(1.f + ed0);
    const float ri1 = __frcp_rn(1.f + ed1);
    const float ri2 = __frcp_rn(1.f + ed2);
    // T[target,source], softmax over target per source column
    const float t00 = ri0;        // P(tgt=0 | src=0)
    const float t10 = ed0 * ri0;  // P(tgt=1 | src=0)
    const float t01 = ed1 * ri1;  // P(tgt=0 | src=1)
    const float t11 = ri1;        // P(tgt=1 | src=1)

    float a0 = ri2;               // alpha (joint, power-of-2 rescaled)
    float a1 = ed2 * ri2;
    float C  = 0.f;               // true log-alpha = log(a) + C

    float* outPred = out;
    float* outPost = out + (size_t)BN * TT * 2;
    float* outSm   = out + (size_t)2 * BN * TT * 2;
    float* sPy0 = g_scratch;
    float* sPy1 = g_scratch + (size_t)TT * BN;
    float* sF0  = g_scratch + (size_t)2 * TT * BN;

    float4 obsReg[8];
    int4   corrReg[4];

    // ---- prologue: load chunk 0, stage to smem ----
    {
        const int c = 0;
#pragma unroll
        for (int i = 0; i < 8; i++) {
            int idx = i * THREADS + tid;
            int r = idx >> 3, p = idx & 7;
            obsReg[i] = *(const float4*)(obs + ((size_t)(row0 + r) * TT + c * TC) * 2 + p * 4);
        }
#pragma unroll
        for (int i = 0; i < 4; i++) {
            int idx = i * THREADS + tid;
            int r = idx >> 2, p = idx & 3;
            corrReg[i] = *(const int4*)(corr + (size_t)(row0 + r) * TT + c * TC + p * 4);
        }
#pragma unroll
        for (int i = 0; i < 8; i++) {
            int idx = i * THREADS + tid;
            int r = idx >> 3, p = idx & 7;
            float4 v = obsReg[i];
            sA[r * SA + p * 4 + 0] = v.x;
            sA[r * SA + p * 4 + 1] = v.y;
            sA[r * SA + p * 4 + 2] = v.z;
            sA[r * SA + p * 4 + 3] = v.w;
        }
#pragma unroll
        for (int i = 0; i < 4; i++) {
            int idx = i * THREADS + tid;
            int r = idx >> 2, p = idx & 3;
            int4 v = corrReg[i];
            sCc[r * SC + p * 4 + 0] = v.x;
            sCc[r * SC + p * 4 + 1] = v.y;
            sCc[r * SC + p * 4 + 2] = v.z;
            sCc[r * SC + p * 4 + 3] = v.w;
        }
        __syncthreads();
    }

    // =========================== FORWARD ===========================
    for (int c = 0; c < NCH; c++) {
        // prefetch next chunk into registers (hidden behind compute)
        if (c + 1 < NCH) {
#pragma unroll
            for (int i = 0; i < 8; i++) {
                int idx = i * THREADS + tid;
                int r = idx >> 3, p = idx & 7;
                obsReg[i] = *(const float4*)(obs + ((size_t)(row0 + r) * TT + (c + 1) * TC) * 2 + p * 4);
            }
#pragma unroll
            for (int i = 0; i < 4; i++) {
                int idx = i * THREADS + tid;
                int r = idx >> 2, p = idx & 3;
                corrReg[i] = *(const int4*)(corr + (size_t)(row0 + r) * TT + (c + 1) * TC + p * 4);
            }
        }

#pragma unroll
        for (int j = 0; j < TC; j++) {
            float o0 = sA[tid * SA + 2 * j];
            float o1 = sA[tid * SA + 2 * j + 1];
            int   y  = sCc[tid * SC + j];

            float e0 = __expf(o0), e1 = __expf(o1);
            float q0 = __frcp_rn(1.f + e0);      // P(y=0|s=0)
            float q1 = __frcp_rn(1.f + e1);      // P(y=1|s=1)
            float w01 = e0 * q0;                 // P(y=1|s=0)
            float w10 = e1 * q1;                 // P(y=0|s=1)

            // predictive (auto-normalized up to the scale of a)
            float pred0 = a0 * q0  + a1 * w10;
            float pred1 = a0 * w01 + a1 * q1;
            float rs = __frcp_rn(pred0 + pred1);
            float lp0 = __logf(pred0 * rs);
            float lp1 = __logf(pred1 * rs);

            float py0 = y ? w01 : q0;
            float py1 = y ? q1  : w10;
            float jj0 = a0 * py0;
            float jj1 = a1 * py1;
            float post0 = __logf(jj0) + C;
            float post1 = __logf(jj1) + C;
            float f0 = jj0 * __frcp_rn(jj0 + jj1);

            int t = c * TC + j;
            sPy0[(size_t)t * BN + row] = py0;
            sPy1[(size_t)t * BN + row] = py1;
            sF0 [(size_t)t * BN + row] = f0;

            // transition
            float na0 = t00 * jj0 + t01 * jj1;
            float na1 = t10 * jj0 + t11 * jj1;
            // exact power-of-2 rescale
            float S = na0 + na1;
            int eb = (__float_as_int(S) >> 23) & 0xFF;
            float sc = __int_as_float((254 - eb) << 23);   // 2^(127-eb)
            a0 = na0 * sc;
            a1 = na1 * sc;
            C += (float)(eb - 127) * 0.69314718055994531f;

            // stage outputs (overwrite consumed obs slots)
            sA[tid * SA + 2 * j]     = lp0;
            sA[tid * SA + 2 * j + 1] = lp1;
            sB[tid * SA + 2 * j]     = post0;
            sB[tid * SA + 2 * j + 1] = post1;
        }
        __syncthreads();

        // coalesced flush of preds + posts
#pragma unroll
        for (int i = 0; i < 32; i++) {
            int idx = i * THREADS + tid;
            int r = idx >> 5, p = idx & 31;
            size_t g = (size_t)(row0 + r) * (TT * 2) + (size_t)c * (TC * 2) + p;
            outPred[g] = sA[r * SA + p];
            outPost[g] = sB[r * SA + p];
        }
        __syncthreads();

        // stage prefetched next chunk
        if (c + 1 < NCH) {
#pragma unroll
            for (int i = 0; i < 8; i++) {
                int idx = i * THREADS + tid;
                int r = idx >> 3, p = idx & 7;
                float4 v = obsReg[i];
                sA[r * SA + p * 4 + 0] = v.x;
                sA[r * SA + p * 4 + 1] = v.y;
                sA[r * SA + p * 4 + 2] = v.z;
                sA[r * SA + p * 4 + 3] = v.w;
            }
#pragma unroll
            for (int i = 0; i < 4; i++) {
                int idx = i * THREADS + tid;
                int r = idx >> 2, p = idx & 3;
                int4 v = corrReg[i];
                sCc[r * SC + p * 4 + 0] = v.x;
                sCc[r * SC + p * 4 + 1] = v.y;
                sCc[r * SC + p * 4 + 2] = v.z;
                sCc[r * SC + p * 4 + 3] = v.w;
            }
        }
        __syncthreads();
    }

    // =========================== BACKWARD ===========================
    float b0 = 1.f, b1 = 1.f;

    float py0r[2][TC], py1r[2][TC], f0r[2][TC];
    // prologue: load last chunk into buffer 0
    {
        const int c = NCH - 1;
#pragma unroll
        for (int j = 0; j < TC; j++) {
            int t = c * TC + j;
            py0r[0][j] = sPy0[(size_t)t * BN + row];
            py1r[0][j] = sPy1[(size_t)t * BN + row];
            f0r [0][j] = sF0 [(size_t)t * BN + row];
        }
    }

    for (int c = NCH - 1; c >= 0; c--) {
        int cur = (NCH - 1 - c) & 1;
        int nxt = cur ^ 1;
        // prefetch chunk c-1 while computing chunk c
        if (c > 0) {
#pragma unroll
            for (int j = 0; j < TC; j++) {
                int t = (c - 1) * TC + j;
                py0r[nxt][j] = sPy0[(size_t)t * BN + row];
                py1r[nxt][j] = sPy1[(size_t)t * BN + row];
                f0r [nxt][j] = sF0 [(size_t)t * BN + row];
            }
        }

#pragma unroll
        for (int j = TC - 1; j >= 0; j--) {
            float f0 = f0r[cur][j];
            float g0 = f0 * b0;
            float g1 = (1.f - f0) * b1;
            float rs = __frcp_rn(g0 + g1);
            float sm0 = __logf(g0 * rs);
            float sm1 = __logf(g1 * rs);
            sA[tid * SA + 2 * j]     = sm0;
            sA[tid * SA + 2 * j + 1] = sm1;

            // beta recursion (to t-1): nb[src] = sum_tgt py[tgt]*b[tgt]*T[tgt,src]
            float u0 = py0r[cur][j] * b0;
            float u1 = py1r[cur][j] * b1;
            float nb0 = t00 * u0 + t10 * u1;
            float nb1 = t01 * u0 + t11 * u1;
            float S = nb0 + nb1;
            int eb = (__float_as_int(S) >> 23) & 0xFF;
            float sc = __int_as_float((254 - eb) << 23);
            b0 = nb0 * sc;
            b1 = nb1 * sc;
        }
        __syncthreads();

#pragma unroll
        for (int i = 0; i < 32; i++) {
            int idx = i * THREADS + tid;
            int r = idx >> 5, p = idx & 31;
            size_t g = (size_t)(row0 + r) * (TT * 2) + (size_t)c * (TC * 2) + p;
            outSm[g] = sA[r * SA + p];
        }
        __syncthreads();
    }
}

extern "C" void kernel_launch(void* const* d_in, const int* in_sizes, int n_in,
                              void* d_out, int out_size)
{
    const int*   corr = (const int*)d_in[0];
    const float* dyn  = (const float*)d_in[1];
    const float* obs  = (const float*)d_in[2];
    float* out = (float*)d_out;

    bkt_kernel<<<BN / THREADS, THREADS>>>(corr, dyn, obs, out);
}

// round 2
// speedup vs baseline: 2.0264x; 2.0264x over previous
#include <cuda_runtime.h>
#include <cstdint>

// BKT 2-state HMM forward-backward, time-segmented matrix scan.
// corr: (B,T) int32 ; dynamics_logits: (B,3) f32 ; obs_logits: (B,T,2) f32
// out: (3,B,T,2) f32 = [output_logprobs, state_posteriors, smoothed]

#define BN      8192
#define TT      1024
#define SEG     16
#define L       64          // TT/SEG
#define TC      16          // staging chunk
#define THREADS 64
#define SA      33
#define SC      17
#define LN2F    0.69314718055994531f

// scratch (t-major planes)
__device__ float g_py0[(size_t)TT * BN];  // |.| = P(y_t|s=0), sign bit = y_t
__device__ float g_py1[(size_t)TT * BN];  //       P(y_t|s=1)
__device__ float g_P[5][SEG * BN];        // P00,P01,P10,P11,E (seg products)
__device__ float g_ab[3][SEG * BN];       // a0,a1,C at segment start
__device__ float g_bb[2][SEG * BN];       // b0,b1 at segment end

__device__ __forceinline__ void trans_from_dyn(const float* __restrict__ dyn, int row,
                                               float& t00, float& t10, float& t01, float& t11)
{
    float d0 = dyn[row * 3 + 0];
    float d1 = dyn[row * 3 + 1];
    float e0 = __expf(d0), e1 = __expf(d1);
    float r0 = __frcp_rn(1.f + e0);
    float r1 = __frcp_rn(1.f + e1);
    t00 = r0; t10 = e0 * r0;   // src=0 column
    t01 = e1 * r1; t11 = r1;   // src=1 column
}

// ---------------- K1: emissions + segment matrix products ----------------
__global__ __launch_bounds__(THREADS, 16)
void k1_products(const int* __restrict__ corr,
                 const float* __restrict__ dyn,
                 const float* __restrict__ obs)
{
    __shared__ float sA[THREADS * SA];
    __shared__ int   sCc[THREADS * SC];

    const int tid  = threadIdx.x;
    const int row0 = blockIdx.x * THREADS;
    const int row  = row0 + tid;
    const int seg  = blockIdx.y;

    float t00, t10, t01, t11;
    trans_from_dyn(dyn, row, t00, t10, t01, t11);

    float A00 = 1.f, A01 = 0.f, A10 = 0.f, A11 = 1.f;
    int   E = 0;

    for (int c = 0; c < L / TC; c++) {
        const int tbase = seg * L + c * TC;
        __syncthreads();
#pragma unroll
        for (int i = 0; i < 8; i++) {
            int idx = i * THREADS + tid;
            int r = idx >> 3, p = idx & 7;
            float4 v = *(const float4*)(obs + ((size_t)(row0 + r) * TT + tbase) * 2 + p * 4);
            sA[r * SA + p * 4 + 0] = v.x;
            sA[r * SA + p * 4 + 1] = v.y;
            sA[r * SA + p * 4 + 2] = v.z;
            sA[r * SA + p * 4 + 3] = v.w;
        }
#pragma unroll
        for (int i = 0; i < 4; i++) {
            int idx = i * THREADS + tid;
            int r = idx >> 2, p = idx & 3;
            int4 v = *(const int4*)(corr + (size_t)(row0 + r) * TT + tbase + p * 4);
            sCc[r * SC + p * 4 + 0] = v.x;
            sCc[r * SC + p * 4 + 1] = v.y;
            sCc[r * SC + p * 4 + 2] = v.z;
            sCc[r * SC + p * 4 + 3] = v.w;
        }
        __syncthreads();

#pragma unroll
        for (int j = 0; j < TC; j++) {
            float o0 = sA[tid * SA + 2 * j];
            float o1 = sA[tid * SA + 2 * j + 1];
            int   y  = sCc[tid * SC + j];

            float e0 = __expf(o0), e1 = __expf(o1);
            float q0 = __frcp_rn(1.f + e0);   // P(y=0|s=0)
            float q1 = __frcp_rn(1.f + e1);   // P(y=1|s=1)
            float w01 = e0 * q0;              // P(y=1|s=0)
            float w10 = e1 * q1;              // P(y=0|s=1)

            float py0 = y ? w01 : q0;
            float py1 = y ? q1  : w10;

            int t = tbase + j;
            g_py0[(size_t)t * BN + row] = __int_as_float(__float_as_int(py0) | (y << 31));
            g_py1[(size_t)t * BN + row] = py1;

            // M = T * diag(py);  Acc' = M * Acc
            float m00 = t00 * py0, m01 = t01 * py1;
            float m10 = t10 * py0, m11 = t11 * py1;
            float n00 = m00 * A00 + m01 * A10;
            float n01 = m00 * A01 + m01 * A11;
            float n10 = m10 * A00 + m11 * A10;
            float n11 = m10 * A01 + m11 * A11;
            float s = (n00 + n01) + (n10 + n11);
            int eb = (__float_as_int(s) >> 23) & 0xFF;
            float sc = __int_as_float((254 - eb) << 23);    // 2^(127-eb)
            A00 = n00 * sc; A01 = n01 * sc; A10 = n10 * sc; A11 = n11 * sc;
            E += eb - 127;
        }
    }

    int gidx = seg * BN + row;
    g_P[0][gidx] = A00; g_P[1][gidx] = A01;
    g_P[2][gidx] = A10; g_P[3][gidx] = A11;
    g_P[4][gidx] = (float)E;
}

// ---------------- K2: boundary scan (alpha forward, beta backward) ----------------
__global__ __launch_bounds__(THREADS)
void k2_scan(const float* __restrict__ dyn)
{
    const int row = blockIdx.x * THREADS + threadIdx.x;

    float d2 = dyn[row * 3 + 2];
    float ed2 = __expf(d2);
    float ri2 = __frcp_rn(1.f + ed2);
    float a0 = ri2, a1 = ed2 * ri2;
    int   Ea = 0;   // exact integer log2-scale; C = Ea * ln2

    for (int k = 0; k < SEG; k++) {
        int gi = k * BN + row;
        g_ab[0][gi] = a0;
        g_ab[1][gi] = a1;
        g_ab[2][gi] = (float)Ea * LN2F;

        float P00 = g_P[0][gi], P01 = g_P[1][gi];
        float P10 = g_P[2][gi], P11 = g_P[3][gi];
        int   Ek  = (int)g_P[4][gi];

        float na0 = P00 * a0 + P01 * a1;
        float na1 = P10 * a0 + P11 * a1;
        float s = na0 + na1;
        int eb = (__float_as_int(s) >> 23) & 0xFF;
        float sc = __int_as_float((254 - eb) << 23);
        a0 = na0 * sc; a1 = na1 * sc;
        Ea += Ek + (eb - 127);
    }

    float b0 = 1.f, b1 = 1.f;
    for (int k = SEG - 1; k >= 0; k--) {
        int gi = k * BN + row;
        g_bb[0][gi] = b0;
        g_bb[1][gi] = b1;
        if (k > 0) {
            float P00 = g_P[0][gi], P01 = g_P[1][gi];
            float P10 = g_P[2][gi], P11 = g_P[3][gi];
            float nb0 = P00 * b0 + P10 * b1;   // P^T * b
            float nb1 = P01 * b0 + P11 * b1;
            float s = nb0 + nb1;
            int eb = (__float_as_int(s) >> 23) & 0xFF;
            float sc = __int_as_float((254 - eb) << 23);
            b0 = nb0 * sc; b1 = nb1 * sc;
        }
    }
}

// ---------------- K3: per-segment output pass ----------------
__global__ __launch_bounds__(THREADS, 8)
void k3_outputs(const float* __restrict__ dyn, float* __restrict__ out)
{
    __shared__ float sA[THREADS * SA];
    __shared__ float sB[THREADS * SA];
    __shared__ float sF[L * THREADS];   // f0 per (t_local, thread)

    const int tid  = threadIdx.x;
    const int row0 = blockIdx.x * THREADS;
    const int row  = row0 + tid;
    const int seg  = blockIdx.y;

    float t00, t10, t01, t11;
    trans_from_dyn(dyn, row, t00, t10, t01, t11);

    float* outPred = out;
    float* outPost = out + (size_t)BN * TT * 2;
    float* outSm   = out + (size_t)2 * BN * TT * 2;

    const int gi = seg * BN + row;
    float a0 = g_ab[0][gi];
    float a1 = g_ab[1][gi];
    float C  = g_ab[2][gi];

    // ---------- forward sub-walk: pred + post + f0 ----------
    for (int c = 0; c < L / TC; c++) {
        const int tbase = seg * L + c * TC;
#pragma unroll
        for (int j = 0; j < TC; j++) {
            int t = tbase + j;
            float p0s = g_py0[(size_t)t * BN + row];
            float py1 = g_py1[(size_t)t * BN + row];
            int   y   = (__float_as_int(p0s) >> 31) & 1;
            float py0 = fabsf(p0s);

            float jj0 = a0 * py0;
            float jj1 = a1 * py1;
            float js  = jj0 + jj1;
            float ns  = a0 * (1.f - py0) + a1 * (1.f - py1);
            float la  = __logf(a0 + a1);
            float lpy = __logf(js) - la;
            float lpo = __logf(ns) - la;
            float lp0 = y ? lpo : lpy;
            float lp1 = y ? lpy : lpo;

            float post0 = __logf(jj0) + C;
            float post1 = __logf(jj1) + C;
            float f0 = jj0 * __frcp_rn(js);
            sF[(c * TC + j) * THREADS + tid] = f0;

            float na0 = t00 * jj0 + t01 * jj1;
            float na1 = t10 * jj0 + t11 * jj1;
            float s = na0 + na1;
            int eb = (__float_as_int(s) >> 23) & 0xFF;
            float sc = __int_as_float((254 - eb) << 23);
            a0 = na0 * sc; a1 = na1 * sc;
            C += (float)(eb - 127) * LN2F;

            sA[tid * SA + 2 * j]     = lp0;
            sA[tid * SA + 2 * j + 1] = lp1;
            sB[tid * SA + 2 * j]     = post0;
            sB[tid * SA + 2 * j + 1] = post1;
        }
        __syncthreads();
#pragma unroll
        for (int i = 0; i < 32; i++) {
            int idx = i * THREADS + tid;
            int r = idx >> 5, p = idx & 31;
            size_t g = (size_t)(row0 + r) * (TT * 2) + (size_t)tbase * 2 + p;
            outPred[g] = sA[r * SA + p];
            outPost[g] = sB[r * SA + p];
        }
        __syncthreads();
    }

    // ---------- backward sub-walk: smoothed ----------
    float b0 = g_bb[0][gi];
    float b1 = g_bb[1][gi];

    for (int c = L / TC - 1; c >= 0; c--) {
        const int tbase = seg * L + c * TC;
#pragma unroll
        for (int j = TC - 1; j >= 0; j--) {
            int t = tbase + j;
            float f0 = sF[(c * TC + j) * THREADS + tid];
            float g0 = f0 * b0;
            float g1 = (1.f - f0) * b1;
            float rs = __frcp_rn(g0 + g1);
            sA[tid * SA + 2 * j]     = __logf(g0 * rs);
            sA[tid * SA + 2 * j + 1] = __logf(g1 * rs);

            float p0s = g_py0[(size_t)t * BN + row];
            float py1 = g_py1[(size_t)t * BN + row];
            float py0 = fabsf(p0s);
            float u0 = py0 * b0;
            float u1 = py1 * b1;
            float nb0 = t00 * u0 + t10 * u1;
            float nb1 = t01 * u0 + t11 * u1;
            float s = nb0 + nb1;
            int eb = (__float_as_int(s) >> 23) & 0xFF;
            float sc = __int_as_float((254 - eb) << 23);
            b0 = nb0 * sc; b1 = nb1 * sc;
        }
        __syncthreads();
#pragma unroll
        for (int i = 0; i < 32; i++) {
            int idx = i * THREADS + tid;
            int r = idx >> 5, p = idx & 31;
            size_t g = (size_t)(row0 + r) * (TT * 2) + (size_t)tbase * 2 + p;
            outSm[g] = sA[r * SA + p];
        }
        __syncthreads();
    }
}

extern "C" void kernel_launch(void* const* d_in, const int* in_sizes, int n_in,
                              void* d_out, int out_size)
{
    const int*   corr = (const int*)d_in[0];
    const float* dyn  = (const float*)d_in[1];
    const float* obs  = (const float*)d_in[2];
    float* out = (float*)d_out;

    dim3 gridSeg(BN / THREADS, SEG);
    k1_products<<<gridSeg, THREADS>>>(corr, dyn, obs);
    k2_scan<<<BN / THREADS, THREADS>>>(dyn);
    k3_outputs<<<gridSeg, THREADS>>>(dyn, out);
}

// round 3
// speedup vs baseline: 3.2518x; 1.6047x over previous
#include <cuda_runtime.h>
#include <cstdint>

// BKT 2-state HMM forward-backward, 64-way time-segmented matrix scan.
// corr: (B,T) int32 ; dynamics_logits: (B,3) f32 ; obs_logits: (B,T,2) f32
// out: (3,B,T,2) f32 = [output_logprobs, state_posteriors, smoothed]

#define BN   8192
#define TT   1024
#define SEG  64
#define L    16
#define LN2F 0.69314718055994531f

__device__ float4 g_P4[SEG * BN];   // segment 2x2 products (A00,A01,A10,A11)
__device__ int    g_E [SEG * BN];   // segment log2 scale
__device__ float4 g_ab[SEG * BN];   // (a0,a1,C,-) normalized alpha at segment start
__device__ float2 g_bb[SEG * BN];   // (b0,b1) beta at segment end

__device__ __forceinline__ void trans_from_dyn(const float* __restrict__ dyn, int row,
                                               float& t00, float& t10, float& t01, float& t11)
{
    float d0 = dyn[row * 3 + 0];
    float d1 = dyn[row * 3 + 1];
    float e0 = __expf(d0), e1 = __expf(d1);
    float r0 = __frcp_rn(1.f + e0);
    float r1 = __frcp_rn(1.f + e1);
    t00 = r0;      t10 = e0 * r0;   // src=0 column (sums to 1)
    t01 = e1 * r1; t11 = r1;        // src=1 column (sums to 1)
}

// ---------------- K1: per-segment 2x2 matrix products ----------------
__global__ __launch_bounds__(256)
void k1_products(const int* __restrict__ corr,
                 const float* __restrict__ dyn,
                 const float* __restrict__ obs)
{
    const int g   = blockIdx.x * 256 + threadIdx.x;   // g = seg*BN + row
    const int row = g & (BN - 1);
    const int seg = g >> 13;

    float t00, t10, t01, t11;
    trans_from_dyn(dyn, row, t00, t10, t01, t11);

    float o[2 * L];
    const float4* op = (const float4*)(obs + ((size_t)row * TT + seg * L) * 2);
#pragma unroll
    for (int i = 0; i < 8; i++) {
        float4 v = op[i];
        o[4 * i + 0] = v.x; o[4 * i + 1] = v.y;
        o[4 * i + 2] = v.z; o[4 * i + 3] = v.w;
    }
    int yb[L];
    const int4* cp = (const int4*)(corr + (size_t)row * TT + seg * L);
#pragma unroll
    for (int i = 0; i < 4; i++) {
        int4 v = cp[i];
        yb[4 * i + 0] = v.x; yb[4 * i + 1] = v.y;
        yb[4 * i + 2] = v.z; yb[4 * i + 3] = v.w;
    }

    float A00 = 1.f, A01 = 0.f, A10 = 0.f, A11 = 1.f;
    int E = 0;
#pragma unroll
    for (int j = 0; j < L; j++) {
        float e0 = __expf(o[2 * j]), e1 = __expf(o[2 * j + 1]);
        float r0 = __frcp_rn(1.f + e0);
        float r1 = __frcp_rn(1.f + e1);
        float py0 = yb[j] ? e0 * r0 : r0;
        float py1 = yb[j] ? r1 : e1 * r1;

        float m00 = t00 * py0, m01 = t01 * py1;
        float m10 = t10 * py0, m11 = t11 * py1;
        float n00 = m00 * A00 + m01 * A10;
        float n01 = m00 * A01 + m01 * A11;
        float n10 = m10 * A00 + m11 * A10;
        float n11 = m10 * A01 + m11 * A11;
        float s = (n00 + n01) + (n10 + n11);
        int eb = (__float_as_int(s) >> 23) & 0xFF;
        float sc = __int_as_float((254 - eb) << 23);
        A00 = n00 * sc; A01 = n01 * sc; A10 = n10 * sc; A11 = n11 * sc;
        E += eb - 127;
    }
    g_P4[g] = make_float4(A00, A01, A10, A11);
    g_E[g]  = E;
}

// ---------------- K2: boundary scan over segments ----------------
__global__ __launch_bounds__(256)
void k2_scan(const float* __restrict__ dyn)
{
    const int row = blockIdx.x * 256 + threadIdx.x;

    float d2 = dyn[row * 3 + 2];
    float ed2 = __expf(d2);
    float ri2 = __frcp_rn(1.f + ed2);
    float a0 = ri2, a1 = ed2 * ri2;
    int Ea = 0;

#pragma unroll 8
    for (int k = 0; k < SEG; k++) {
        int gi = k * BN + row;
        float s  = a0 + a1;
        float rs = __frcp_rn(s);
        float C  = (float)Ea * LN2F + __logf(s);
        g_ab[gi] = make_float4(a0 * rs, a1 * rs, C, 0.f);

        float4 P = g_P4[gi];
        int Ek   = g_E[gi];
        float na0 = P.x * a0 + P.y * a1;
        float na1 = P.z * a0 + P.w * a1;
        float ss = na0 + na1;
        int eb = (__float_as_int(ss) >> 23) & 0xFF;
        float sc = __int_as_float((254 - eb) << 23);
        a0 = na0 * sc; a1 = na1 * sc;
        Ea += Ek + (eb - 127);
    }

    float b0 = 1.f, b1 = 1.f;
#pragma unroll 8
    for (int k = SEG - 1; k >= 1; k--) {
        int gi = k * BN + row;
        g_bb[gi] = make_float2(b0, b1);
        float4 P = g_P4[gi];
        float nb0 = P.x * b0 + P.z * b1;   // P^T * b
        float nb1 = P.y * b0 + P.w * b1;
        float ss = nb0 + nb1;
        int eb = (__float_as_int(ss) >> 23) & 0xFF;
        float sc = __int_as_float((254 - eb) << 23);
        b0 = nb0 * sc; b1 = nb1 * sc;
    }
    g_bb[row] = make_float2(b0, b1);
}

// ---------------- K3: per-segment outputs (normalized filter) ----------------
__global__ __launch_bounds__(64, 8)
void k3_outputs(const int* __restrict__ corr,
                const float* __restrict__ dyn,
                const float* __restrict__ obs,
                float* __restrict__ out)
{
    __shared__ float sA[64 * 33];
    __shared__ float sB[64 * 33];

    const int tid  = threadIdx.x;
    const int row0 = blockIdx.x * 64;
    const int row  = row0 + tid;
    const int seg  = blockIdx.y;

    float t00, t10, t01, t11;
    trans_from_dyn(dyn, row, t00, t10, t01, t11);

    float* outPred = out;
    float* outPost = out + (size_t)BN * TT * 2;
    float* outSm   = out + (size_t)2 * BN * TT * 2;

    float o[2 * L];
    const float4* op = (const float4*)(obs + ((size_t)row * TT + seg * L) * 2);
#pragma unroll
    for (int i = 0; i < 8; i++) {
        float4 v = op[i];
        o[4 * i + 0] = v.x; o[4 * i + 1] = v.y;
        o[4 * i + 2] = v.z; o[4 * i + 3] = v.w;
    }
    unsigned ymask = 0;
    const int4* cp = (const int4*)(corr + (size_t)row * TT + seg * L);
#pragma unroll
    for (int i = 0; i < 4; i++) {
        int4 v = cp[i];
        ymask |= (unsigned)(v.x & 1) << (4 * i + 0);
        ymask |= (unsigned)(v.y & 1) << (4 * i + 1);
        ymask |= (unsigned)(v.z & 1) << (4 * i + 2);
        ymask |= (unsigned)(v.w & 1) << (4 * i + 3);
    }

    const int gi = seg * BN + row;
    float4 ab = g_ab[gi];
    float a0 = ab.x, a1 = ab.y, C = ab.z;

    float f0s[L];

    // ---- forward: pred + post + f0 ----
#pragma unroll
    for (int j = 0; j < L; j++) {
        int y = (ymask >> j) & 1;
        float e0 = __expf(o[2 * j]), e1 = __expf(o[2 * j + 1]);
        float r0 = __frcp_rn(1.f + e0);
        float r1 = __frcp_rn(1.f + e1);
        float s0a = r0, s0b = e0 * r0;       // P(y=0|s=0), P(y=1|s=0)
        float s1a = e1 * r1, s1b = r1;       // P(y=0|s=1), P(y=1|s=1)
        float py0 = y ? s0b : s0a;           // emission of observed symbol
        float py1 = y ? s1b : s1a;
        float pn0 = y ? s0a : s0b;           // emission of the other symbol
        float pn1 = y ? s1a : s1b;

        float jj0 = a0 * py0;
        float jj1 = a1 * py1;
        float js  = jj0 + jj1;               // predictive prob of observed symbol
        float ns  = a0 * pn0 + a1 * pn1;     // predictive prob of other symbol
        float ljs = __logf(js);
        float lns = __logf(ns);
        float lp0 = y ? lns : ljs;
        float lp1 = y ? ljs : lns;
        float post0 = __logf(jj0) + C;
        float post1 = __logf(jj1) + C;

        float f = jj0 * __frcp_rn(js);
        f0s[j] = f;
        float fc = 1.f - f;
        a0 = t00 * f + t01 * fc;             // stays normalized (columns of T sum to 1)
        a1 = t10 * f + t11 * fc;
        C += ljs;

        sA[tid * 33 + 2 * j]     = lp0;
        sA[tid * 33 + 2 * j + 1] = lp1;
        sB[tid * 33 + 2 * j]     = post0;
        sB[tid * 33 + 2 * j + 1] = post1;
    }
    __syncthreads();
#pragma unroll
    for (int i = 0; i < 8; i++) {
        int idx = i * 64 + tid;
        int r = idx >> 5, p = idx & 31;
        size_t g = (size_t)(row0 + r) * (TT * 2) + (size_t)seg * (L * 2) + p;
        outPred[g] = sA[r * 33 + p];
        outPost[g] = sB[r * 33 + p];
        int r2 = r + 16;
        size_t g2 = (size_t)(row0 + r2) * (TT * 2) + (size_t)seg * (L * 2) + p;
        outPred[g2] = sA[r2 * 33 + p];
        outPost[g2] = sB[r2 * 33 + p];
        int r3 = r + 32;
        size_t g3 = (size_t)(row0 + r3) * (TT * 2) + (size_t)seg * (L * 2) + p;
        outPred[g3] = sA[r3 * 33 + p];
        outPost[g3] = sB[r3 * 33 + p];
        int r4 = r + 48;
        size_t g4 = (size_t)(row0 + r4) * (TT * 2) + (size_t)seg * (L * 2) + p;
        outPred[g4] = sA[r4 * 33 + p];
        outPost[g4] = sB[r4 * 33 + p];
    }
    __syncthreads();

    // ---- backward: smoothed ----
    float2 bb = g_bb[gi];
    float b0 = bb.x, b1 = bb.y;

#pragma unroll
    for (int j = L - 1; j >= 0; j--) {
        float f = f0s[j];
        float g0 = f * b0;
        float g1 = (1.f - f) * b1;
        float rs = __frcp_rn(g0 + g1);
        sA[tid * 33 + 2 * j]     = __logf(g0 * rs);
        sA[tid * 33 + 2 * j + 1] = __logf(g1 * rs);

        int y = (ymask >> j) & 1;
        float e0 = __expf(o[2 * j]), e1 = __expf(o[2 * j + 1]);
        float r0 = __frcp_rn(1.f + e0);
        float r1 = __frcp_rn(1.f + e1);
        float py0 = y ? e0 * r0 : r0;
        float py1 = y ? r1 : e1 * r1;
        float u0 = py0 * b0;
        float u1 = py1 * b1;
        float nb0 = t00 * u0 + t10 * u1;
        float nb1 = t01 * u0 + t11 * u1;
        float ss = nb0 + nb1;
        int eb = (__float_as_int(ss) >> 23) & 0xFF;
        float sc = __int_as_float((254 - eb) << 23);
        b0 = nb0 * sc; b1 = nb1 * sc;
    }
    __syncthreads();
#pragma unroll
    for (int i = 0; i < 32; i++) {
        int idx = i * 64 + tid;
        int r = idx >> 5, p = idx & 31;
        size_t g = (size_t)(row0 + r) * (TT * 2) + (size_t)seg * (L * 2) + p;
        outSm[g] = sA[r * 33 + p];
    }
}

extern "C" void kernel_launch(void* const* d_in, const int* in_sizes, int n_in,
                              void* d_out, int out_size)
{
    const int*   corr = (const int*)d_in[0];
    const float* dyn  = (const float*)d_in[1];
    const float* obs  = (const float*)d_in[2];
    float* out = (float*)d_out;

    k1_products<<<(BN * SEG) / 256, 256>>>(corr, dyn, obs);
    k2_scan<<<BN / 256, 256>>>(dyn);
    dim3 g3(BN / 64, SEG);
    k3_outputs<<<g3, 64>>>(corr, dyn, obs, out);
}